// round 14
// baseline (speedup 1.0000x reference)
#include <cuda_runtime.h>
#include <cooperative_groups.h>
#include <math.h>

namespace cg = cooperative_groups;

// logZ of Conditional Poisson = log ESP_K(exp(w)), D=8192, K=256.
//
// ONE kernel, cluster of 4 CTAs x 512 threads, stateless.
// Tilted linear domain (x' = exp(w - B), B = 4.40625); all convolutions are
// fp32 FMA dot products over two-sided degree windows. Critical-path-
// minimized: the lower tree (8..128 items) is WARP-LOCAL (each warp owns 32
// leaves in a private smem slab; __syncwarp only), then 4 block levels
// (__syncthreads), then cluster mbarrier push-flows. Subtree output scaled
// by exact 2^-62 (range-safe: worst case e^66 < e^88).
//  Stage 1 (all CTAs): 2048-item subtree -> 93-coeff poly [18,110] in smem.
//  Stage 2: CTAs 2,3 push to CTAs 0,1 (mbarrier, exit); 0,1 conv -> L9 poly
//           [66,190].
//  Stage 3: CTA 1 pushes L9 to CTA 0; CTA 0: c_K dot + log + 248ln2 + K*B.

#define FULL  0xffffffffu
#define BTILT 4.40625f                  // 256*B = 1128.0 exact
#define THR   512
#define NCTA  4
#define SCALE 2.168404344971009e-19f    // 2^-62 exact
#define LGSUM 171.9005008f              // 248 * ln(2)

// Warp-local conv: NP dest polys from 2*NP sources, windows [0,SHI_S]->[0,SHI_D].
template<int SHI_S, int SHI_D, int NP>
__device__ __forceinline__ void wconv(const float* __restrict__ src,
                                      float* __restrict__ dst, int lane)
{
    constexpr int SST   = SHI_S + 1;
    constexpr int DSTR  = SHI_D + 1;
    constexpr int NTASK = NP * DSTR;
    for (int t = lane; t < NTASK; t += 32) {
        const int p = t / DSTR;               // literal divisor -> mul/shift
        const int j = t - p * DSTR;
        const float* a = src + (2 * p) * SST;
        const float* b = a + SST;
        const int ilo = (j - SHI_S > 0) ? j - SHI_S : 0;
        const int ihi = (j < SHI_S) ? j : SHI_S;
        float s = 0.f;
        #pragma unroll 4
        for (int i = ilo; i <= ihi; ++i) s = fmaf(a[i], b[j - i], s);
        dst[p * DSTR + j] = s;
    }
}

// Block-level conv (R12-validated form).
template<int SHI_S, int SLO_D, int SHI_D, int NP>
__device__ __forceinline__ void conv_lvl(const float* __restrict__ src,
                                         float* __restrict__ dst, int tid)
{
    constexpr int SST   = SHI_S + 1;
    constexpr int DSTR  = SHI_D - SLO_D + 1;
    constexpr int NTASK = NP * DSTR;
    for (int t = tid; t < NTASK; t += THR) {
        const int p  = t / DSTR;
        const int jj = t - p * DSTR;
        const int j  = jj + SLO_D;
        const float* a = src + (2 * p) * SST;
        const float* b = a + SST;
        const int ilo = (j - SHI_S > 0) ? j - SHI_S : 0;
        const int ihi = (j < SHI_S) ? j : SHI_S;
        const float* ap = a + ilo;
        const float* bp = b + (j - ilo);
        const int len = ihi - ilo + 1;
        float s0 = 0.f, s1 = 0.f;
        int q = 0;
        #pragma unroll 2
        for (; q + 2 <= len; q += 2) {
            s0 = fmaf(ap[q],     bp[-q],     s0);
            s1 = fmaf(ap[q + 1], bp[-q - 1], s1);
        }
        if (q < len) s0 = fmaf(ap[q], bp[-q], s0);
        dst[p * DSTR + jj] = s0 + s1;
    }
}

__global__ __launch_bounds__(THR) __cluster_dims__(NCTA, 1, 1)
void cp_kernel(const float* __restrict__ w,
               const int* __restrict__ Kp,
               float* __restrict__ out)
{
    __shared__ float WA[16 * 160];  // per-warp slab: L0 32x5 | L2 8x9 | L4 2x16
    __shared__ float WB[16 * 96];   // per-warp slab: L1 16x6 | L3 4x13
    __shared__ float G0[16 * 21];   // 16 x 128-item polys [0,20]
    __shared__ float G1[8 * 29];    // 8 x 256-item [0,28]
    __shared__ float G2[4 * 43];    // 4 x 512-item [0,42]
    __shared__ float G3[2 * 67];    // 2 x 1024-item [0,66]
    __shared__ float pub[93];       // own subtree poly [18,110], scaled
    __shared__ float recv[93];      // partner's pushed poly (CTAs 0,1)
    __shared__ float fin[2 * 125];  // CTA 0: both L9 polys [66,190]
    __shared__ __align__(8) unsigned long long barL9, barFin;

    cg::cluster_group cl = cg::this_cluster();
    const int rank = (int)blockIdx.x;
    const int tid  = threadIdx.x;
    const int lane = tid & 31;
    const int warp = tid >> 5;

    const unsigned int barL9_u32  = (unsigned int)__cvta_generic_to_shared(&barL9);
    const unsigned int barFin_u32 = (unsigned int)__cvta_generic_to_shared(&barFin);

    if (tid == 0) {
        asm volatile("mbarrier.init.shared.b64 [%0], %1;"
                     :: "r"(barL9_u32), "r"(1u) : "memory");
        asm volatile("mbarrier.init.shared.b64 [%0], %1;"
                     :: "r"(barFin_u32), "r"(1u) : "memory");
    }
    asm volatile("barrier.cluster.arrive.aligned;" ::: "memory");

    float* wa = WA + warp * 160;
    float* wb = WB + warp * 96;

    // ---- Stage 1a: leaf DP, each lane -> 4 items, ESP_0..4 exact ----
    {
        const float4 wv = ((const float4*)(w + rank * 2048))[tid];
        const float xs[4] = {wv.x, wv.y, wv.z, wv.w};
        float c1 = 0, c2 = 0, c3 = 0, c4 = 0;
        #pragma unroll
        for (int k = 0; k < 4; ++k) {
            const float x = __expf(xs[k] - BTILT);
            c4 = fmaf(x, c3, c4);
            c3 = fmaf(x, c2, c3);
            c2 = fmaf(x, c1, c2);
            c1 += x;
        }
        float* d = wa + lane * 5;
        d[0] = 1.f; d[1] = c1; d[2] = c2; d[3] = c3; d[4] = c4;
    }
    __syncwarp();

    // ---- Stage 1b: warp-local tree 4 -> 128 items (syncwarp only) ----
    wconv< 4,  5, 16>(wa, wb, lane); __syncwarp();
    wconv< 5,  8,  8>(wb, wa, lane); __syncwarp();
    wconv< 8, 12,  4>(wa, wb, lane); __syncwarp();
    wconv<12, 15,  2>(wb, wa, lane); __syncwarp();
    wconv<15, 20,  1>(wa, G0 + warp * 21, lane);
    __syncthreads();

    // ---- Stage 1c: block tree 128 -> 1024 items ----
    conv_lvl<20, 0, 28, 8>(G0, G1, tid); __syncthreads();
    conv_lvl<28, 0, 42, 4>(G1, G2, tid); __syncthreads();
    conv_lvl<42, 0, 66, 2>(G2, G3, tid); __syncthreads();

    // ---- Stage 1d: 2x[0,66] -> [18,110], scaled 2^-62, pair-split ----
    {
        const bool act = tid < 186;                 // 93 outputs x 2 lanes
        const int  u   = tid >> 1, r = tid & 1;
        const int  j   = (act ? u : 0) + 18;
        const float* a = G3;                        // poly 0
        const float* b = G3 + 67;                   // poly 1
        const int ilo = (j - 66 > 0) ? j - 66 : 0;
        const int ihi = (j < 66) ? j : 66;
        const float* ap = a + ilo + r;
        const float* bp = b + (j - ilo) - r;
        const int len = act ? (ihi - ilo + 1 - r) : 0;
        float s0 = 0.f, s1 = 0.f;
        int q = 0;
        #pragma unroll 2
        for (; q + 4 <= len; q += 4) {
            s0 = fmaf(ap[q],     bp[-q],     s0);
            s1 = fmaf(ap[q + 2], bp[-q - 2], s1);
        }
        if (q < len)     s0 = fmaf(ap[q],     bp[-q],     s0);
        if (q + 2 < len) s1 = fmaf(ap[q + 2], bp[-q - 2], s1);
        float s = s0 + s1;
        s += __shfl_xor_sync(FULL, s, 1);
        if (act && r == 0) pub[u] = s * SCALE;
    }
    __syncthreads();

    // ---- complete the split cluster barrier (bars + pub all ready) ----
    asm volatile("barrier.cluster.wait.aligned;" ::: "memory");

    // ---- Stage 2 producers: CTAs 2,3 push to CTA rank-2 and exit ----
    if (rank >= 2) {
        float* dst = cl.map_shared_rank(recv, rank - 2);
        if (tid < 93) dst[tid] = pub[tid];
        __syncthreads();
        if (tid == 0) {
            asm volatile("fence.acq_rel.cluster;" ::: "memory");
            asm volatile("{\n\t.reg .b32 ra;\n\t"
                         "mapa.shared::cluster.u32 ra, %0, %1;\n\t"
                         "mbarrier.arrive.shared::cluster.b64 _, [ra];\n\t}"
                         :: "r"(barL9_u32), "r"(rank - 2) : "memory");
        }
        return;
    }

    // ---- Stage 2 consumers: CTAs 0,1 wait, then build L9 [66,190] ----
    if (tid == 0) {
        unsigned int done = 0;
        while (!done)
            asm volatile("{\n\t.reg .pred p;\n\t"
                "mbarrier.try_wait.parity.acquire.cluster.shared::cta.b64 "
                "p, [%1], %2, 0x989680;\n\t"
                "selp.b32 %0, 1, 0, p;\n\t}"
                : "=r"(done) : "r"(barL9_u32), "r"(0u) : "memory");
    }
    __syncthreads();

    {   // L9: pub (x) recv, 125 outputs x 4-way lane split (500 active)
        const bool act = tid < 500;
        const int  u   = tid >> 2, r = tid & 3;
        const int  j   = (act ? u : 0) + 66;
        const int ilo = (j - 110 > 18) ? j - 110 : 18;
        const int ihi = (j - 18 < 110) ? j - 18 : 110;
        const float* ap = pub  + (ilo - 18) + r;
        const float* bp = recv + (j - ilo - 18) - r;
        const int len = act ? (ihi - ilo + 1 - r) : 0;
        float s = 0.f;
        #pragma unroll 2
        for (int q = 0; q < len; q += 4) s = fmaf(ap[q], bp[-q], s);
        s += __shfl_xor_sync(FULL, s, 1);
        s += __shfl_xor_sync(FULL, s, 2);
        if (act && r == 0) {
            if (rank == 0) fin[u] = s;
            else           cl.map_shared_rank(fin, 0)[125 + u] = s;
        }
    }

    if (rank == 1) {        // push done; signal CTA 0 and exit
        __syncthreads();
        if (tid == 0) {
            asm volatile("fence.acq_rel.cluster;" ::: "memory");
            asm volatile("{\n\t.reg .b32 ra;\n\t"
                         "mapa.shared::cluster.u32 ra, %0, %1;\n\t"
                         "mbarrier.arrive.shared::cluster.b64 _, [ra];\n\t}"
                         :: "r"(barFin_u32), "r"(0u) : "memory");
        }
        return;
    }

    // ---- Stage 3: CTA 0 waits for CTA 1's L9, then final dot ----
    __syncthreads();
    if (tid == 0) {
        unsigned int done = 0;
        while (!done)
            asm volatile("{\n\t.reg .pred p;\n\t"
                "mbarrier.try_wait.parity.acquire.cluster.shared::cta.b64 "
                "p, [%1], %2, 0x989680;\n\t"
                "selp.b32 %0, 1, 0, p;\n\t}"
                : "=r"(done) : "r"(barFin_u32), "r"(0u) : "memory");
    }
    __syncthreads();

    if (warp == 0) {
        int K = Kp ? *Kp : 256;
        K = min(max(K, 0), 256);
        const float* a = fin;           // L9 poly 0, coeffs [66,190]
        const float* b = fin + 125;     // L9 poly 1
        const int ilo = max(66, K - 190);
        const int ihi = min(190, K - 66);
        float s = 0.f;
        for (int i = ilo + lane; i <= ihi; i += 32)
            s += a[i - 66] * b[K - i - 66];
        #pragma unroll
        for (int o = 16; o; o >>= 1) s += __shfl_xor_sync(FULL, s, o);
        if (lane == 0)
            out[0] = __logf(s) + LGSUM + (float)K * BTILT;
    }
}

extern "C" void kernel_launch(void* const* d_in, const int* in_sizes, int n_in,
                              void* d_out, int out_size) {
    const float* w   = (const float*)d_in[0];
    const int*   Kp  = (n_in >= 2) ? (const int*)d_in[1] : nullptr;
    float*       out = (float*)d_out;
    (void)in_sizes; (void)out_size;
    cp_kernel<<<NCTA, THR>>>(w, Kp, out);
}

// round 15
// speedup vs baseline: 1.1057x; 1.1057x over previous
#include <cuda_runtime.h>
#include <cooperative_groups.h>
#include <math.h>

namespace cg = cooperative_groups;

// logZ of Conditional Poisson = log ESP_K(exp(w)), D=8192, K=256.
//
// ONE kernel, cluster of 8 CTAs x 512 threads, stateless.
// Tilted linear domain (x' = exp(w - B), B = 4.40625); all convolutions are
// fp32 FMA dot products over validated two-sided degree windows.
// Critical-path-minimized: ONE cross-CTA handshake. Every CTA builds the
// [0,66] poly of its 1024 items (leaf-16 DP + 6 conv levels) and st.async's
// the 67 floats straight into CTA 0's smem with mbarrier complete_tx
// accounting (no cluster fence, no producer wait — store and exit).
// CTA 0 waits for 8*67*4 = 2144 tx bytes, then:
//   T1: 8 -> 4 polys, [0,66]^2 -> [18,110], output scaled by exact 2^-62
//   T2: 4 -> 2 polys, [18,110]^2 -> [66,190]
//   final: c_K = dot of the two [66,190] windows; out = log + 248ln2 + K*B.

#define FULL  0xffffffffu
#define BTILT 4.40625f                  // 256*B = 1128.0 exact
#define THR   512
#define NCTA  8
#define SCALE 2.168404344971009e-19f    // 2^-62 exact
#define LGSUM 171.9005008f              // 248 * ln(2)
#define TXBYTES (NCTA * 67 * 4)         // 2144

// Block-level conv (validated): NP dest polys from 2*NP sources,
// windows [0,SHI_S] -> [0,SHI_D].
template<int SHI_S, int SHI_D, int NP>
__device__ __forceinline__ void conv_lvl(const float* __restrict__ src,
                                         float* __restrict__ dst, int tid)
{
    constexpr int SST   = SHI_S + 1;
    constexpr int DSTR  = SHI_D + 1;
    constexpr int NTASK = NP * DSTR;    // always <= THR here
    const int t = tid;
    if (t < NTASK) {
        const int p = t / DSTR;         // constexpr divisor -> mul/shift
        const int j = t - p * DSTR;
        const float* a = src + (2 * p) * SST;
        const float* b = a + SST;
        const int ilo = (j - SHI_S > 0) ? j - SHI_S : 0;
        const int ihi = (j < SHI_S) ? j : SHI_S;
        const float* ap = a + ilo;
        const float* bp = b + (j - ilo);
        const int len = ihi - ilo + 1;
        float s0 = 0.f, s1 = 0.f;
        int q = 0;
        #pragma unroll 2
        for (; q + 2 <= len; q += 2) {
            s0 = fmaf(ap[q],     bp[-q],     s0);
            s1 = fmaf(ap[q + 1], bp[-q - 1], s1);
        }
        if (q < len) s0 = fmaf(ap[q], bp[-q], s0);
        dst[p * DSTR + j] = s0 + s1;
    }
}

__global__ __launch_bounds__(THR) __cluster_dims__(NCTA, 1, 1)
void cp_kernel(const float* __restrict__ w,
               const int* __restrict__ Kp,
               float* __restrict__ out)
{
    __shared__ float A_[576];       // leaf 64x9 | V1 16x16 | V3 4x29
    __shared__ float B_[416];       // V0 32x13  | V2 8x21  | V4 2x43
    __shared__ float recv[NCTA*67]; // CTA 0: the 8 subtree polys [0,66]
    __shared__ float T1s[4 * 93];   // CTA 0: 4 polys [18,110] (scaled)
    __shared__ float T2s[2 * 125];  // CTA 0: 2 polys [66,190]
    __shared__ int   sK;
    __shared__ __align__(8) unsigned long long bar;

    cg::cluster_group cl = cg::this_cluster();
    const int rank = (int)blockIdx.x;
    const int tid  = threadIdx.x;
    const int lane = tid & 31;
    const int warp = tid >> 5;

    const unsigned int bar_u32 = (unsigned int)__cvta_generic_to_shared(&bar);

    // Rank 0: mbarrier init + expect_tx BEFORE the cluster arrive, so the
    // (release) arrive + producers' wait orders it before any st.async.
    if (rank == 0 && tid == 0) {
        asm volatile("mbarrier.init.shared.b64 [%0], %1;"
                     :: "r"(bar_u32), "r"(1u) : "memory");
        asm volatile("mbarrier.arrive.expect_tx.shared.b64 _, [%0], %1;"
                     :: "r"(bar_u32), "r"((unsigned int)TXBYTES) : "memory");
        sK = Kp ? *Kp : 256;           // prefetch K (hides gmem latency)
    }
    asm volatile("barrier.cluster.arrive.aligned;" ::: "memory");

    // ---- Leaf DP: 64 threads x 16 items, ESP_0..8 in registers ----
    if (tid < 64) {
        const float4* wp = (const float4*)(w + rank * 1024 + tid * 16);
        float c1=0,c2=0,c3=0,c4=0,c5=0,c6=0,c7=0,c8=0;
        #pragma unroll
        for (int q = 0; q < 4; ++q) {
            const float4 wv = wp[q];
            const float xs[4] = {wv.x, wv.y, wv.z, wv.w};
            #pragma unroll
            for (int k = 0; k < 4; ++k) {
                const float x = __expf(xs[k] - BTILT);
                c8 = fmaf(x, c7, c8);
                c7 = fmaf(x, c6, c7);
                c6 = fmaf(x, c5, c6);
                c5 = fmaf(x, c4, c5);
                c4 = fmaf(x, c3, c4);
                c3 = fmaf(x, c2, c3);
                c2 = fmaf(x, c1, c2);
                c1 += x;
            }
        }
        float* d = A_ + tid * 9;
        d[0]=1.f; d[1]=c1; d[2]=c2; d[3]=c3; d[4]=c4;
        d[5]=c5;  d[6]=c6; d[7]=c7; d[8]=c8;
    }
    __syncthreads();

    // ---- In-CTA conv ladder: 16 -> 512 items ----
    conv_lvl< 8, 12, 32>(A_, B_, tid); __syncthreads();
    conv_lvl<12, 15, 16>(B_, A_, tid); __syncthreads();
    conv_lvl<15, 20,  8>(A_, B_, tid); __syncthreads();
    conv_lvl<20, 28,  4>(B_, A_, tid); __syncthreads();
    conv_lvl<28, 42,  2>(A_, B_, tid); __syncthreads();

    // producers must not st.async before rank 0's init+expect_tx
    asm volatile("barrier.cluster.wait.aligned;" ::: "memory");

    // ---- V5: 2x[0,42] -> [0,66]; st.async results into CTA 0's recv ----
    {
        const bool act = tid < 134;            // 67 outputs x 2 lanes
        const int  u   = tid >> 1, r = tid & 1;
        const int  j   = act ? u : 0;
        const float* a = B_;                   // poly 0 [0,42]
        const float* b = B_ + 43;              // poly 1
        const int ilo = (j - 42 > 0) ? j - 42 : 0;
        const int ihi = (j < 42) ? j : 42;
        const float* ap = a + ilo + r;
        const float* bp = b + (j - ilo) - r;
        const int len = act ? (ihi - ilo + 1 - r) : 0;
        float s0 = 0.f, s1 = 0.f;
        int q = 0;
        #pragma unroll 2
        for (; q + 4 <= len; q += 4) {
            s0 = fmaf(ap[q],     bp[-q],     s0);
            s1 = fmaf(ap[q + 2], bp[-q - 2], s1);
        }
        if (q < len)     s0 = fmaf(ap[q],     bp[-q],     s0);
        if (q + 2 < len) s1 = fmaf(ap[q + 2], bp[-q - 2], s1);
        float s = s0 + s1;
        s += __shfl_xor_sync(FULL, s, 1);
        if (act && r == 0) {
            // remote smem addr of recv[rank*67 + u] and of bar, in CTA 0
            const unsigned int laddr = (unsigned int)__cvta_generic_to_shared(
                                           &recv[rank * 67 + u]);
            asm volatile(
                "{\n\t.reg .b32 ra, rb;\n\t"
                "mapa.shared::cluster.u32 ra, %0, 0;\n\t"
                "mapa.shared::cluster.u32 rb, %1, 0;\n\t"
                "st.async.shared::cluster.mbarrier::complete_tx::bytes.b32 "
                "[ra], %2, [rb];\n\t}"
                :: "r"(laddr), "r"(bar_u32), "f"(s) : "memory");
        }
    }

    if (rank != 0) return;                     // producers: store-and-exit

    // ---- CTA 0: wait for all 2144 tx bytes (includes its own) ----
    if (tid == 0) {
        unsigned int done = 0;
        while (!done)
            asm volatile("{\n\t.reg .pred p;\n\t"
                "mbarrier.try_wait.parity.acquire.cluster.shared::cta.b64 "
                "p, [%1], %2, 0x989680;\n\t"
                "selp.b32 %0, 1, 0, p;\n\t}"
                : "=r"(done) : "r"(bar_u32), "r"(0u) : "memory");
    }
    __syncthreads();

    // ---- T1: 4 pair-convs, [0,66]^2 -> [18,110], scaled 2^-62 ----
    if (tid < 372) {                           // 4 x 93 outputs, 1/thread
        const int p  = tid / 93;
        const int jj = tid - p * 93;
        const int j  = jj + 18;
        const float* a = recv + (2 * p) * 67;
        const float* b = a + 67;
        const int ilo = (j - 66 > 0) ? j - 66 : 0;
        const int ihi = (j < 66) ? j : 66;
        const float* ap = a + ilo;
        const float* bp = b + (j - ilo);
        const int len = ihi - ilo + 1;
        float s0 = 0.f, s1 = 0.f;
        int q = 0;
        #pragma unroll 2
        for (; q + 2 <= len; q += 2) {
            s0 = fmaf(ap[q],     bp[-q],     s0);
            s1 = fmaf(ap[q + 1], bp[-q - 1], s1);
        }
        if (q < len) s0 = fmaf(ap[q], bp[-q], s0);
        T1s[p * 93 + jj] = (s0 + s1) * SCALE;
    }
    __syncthreads();

    // ---- T2: 2 pair-convs, [18,110]^2 -> [66,190], 2-way lane split ----
    {
        const bool act = tid < 500;            // 250 outputs x 2 lanes
        const int  u   = tid >> 1, r = tid & 1;
        const int  p   = act ? (u / 125) : 0;
        const int  jj  = act ? (u - p * 125) : 0;
        const int  j   = jj + 66;
        const float* a = T1s + (2 * p) * 93;
        const float* b = a + 93;
        const int ilo = (j - 110 > 18) ? j - 110 : 18;
        const int ihi = (j - 18 < 110) ? j - 18 : 110;
        const float* ap = a + (ilo - 18) + r;
        const float* bp = b + (j - ilo - 18) - r;
        const int len = act ? (ihi - ilo + 1 - r) : 0;
        float s0 = 0.f, s1 = 0.f;
        int q = 0;
        #pragma unroll 2
        for (; q + 4 <= len; q += 4) {
            s0 = fmaf(ap[q],     bp[-q],     s0);
            s1 = fmaf(ap[q + 2], bp[-q - 2], s1);
        }
        if (q < len)     s0 = fmaf(ap[q],     bp[-q],     s0);
        if (q + 2 < len) s1 = fmaf(ap[q + 2], bp[-q - 2], s1);
        float s = s0 + s1;
        s += __shfl_xor_sync(FULL, s, 1);
        if (act && r == 0) T2s[p * 125 + jj] = s;
    }
    __syncthreads();

    // ---- Final: c_K from the two [66,190] windows ----
    if (warp == 0) {
        int K = min(max(sK, 0), 256);
        const float* a = T2s;            // poly 0
        const float* b = T2s + 125;      // poly 1
        const int ilo = max(66, K - 190);
        const int ihi = min(190, K - 66);
        float s = 0.f;
        for (int i = ilo + lane; i <= ihi; i += 32)
            s += a[i - 66] * b[K - i - 66];
        #pragma unroll
        for (int o = 16; o; o >>= 1) s += __shfl_xor_sync(FULL, s, o);
        if (lane == 0)
            out[0] = __logf(s) + LGSUM + (float)K * BTILT;
    }
}

extern "C" void kernel_launch(void* const* d_in, const int* in_sizes, int n_in,
                              void* d_out, int out_size) {
    const float* w   = (const float*)d_in[0];
    const int*   Kp  = (n_in >= 2) ? (const int*)d_in[1] : nullptr;
    float*       out = (float*)d_out;
    (void)in_sizes; (void)out_size;
    cp_kernel<<<NCTA, THR>>>(w, Kp, out);
}

// round 17
// speedup vs baseline: 1.1930x; 1.0789x over previous
#include <cuda_runtime.h>
#include <cooperative_groups.h>
#include <math.h>

namespace cg = cooperative_groups;

// logZ of Conditional Poisson = log ESP_K(exp(w)), D=8192, K=256.
//
// ONE kernel, cluster of 8 CTAs x 768 threads, stateless.
// Tilted linear domain (x' = exp(w - B), B = 4.40625); all convolutions are
// fp32 FMA dot products over validated two-sided degree windows, with
// LANE-SPLIT parallel dot products (SPLIT lanes per output + shfl reduce)
// to minimize serial chain length on the critical path (kernel runs at
// idle clock; cycles on the path are the only currency).
// ONE cross-CTA handshake: every CTA st.asyncs its 67-coeff [0,66] subtree
// poly into CTA 0's smem with mbarrier complete_tx accounting; producers
// store-and-exit. CTA 0 then: T1 (8->4, [18,110], x2^-62), T2 (4->2,
// [66,190]), final c_K dot; out = log(c_K) + 248ln2 + K*B.
//
// R16 bug fixed here: conv_split's 2-accumulator loop (q += 2*SPLIT) can
// leave TWO tail elements per lane (q and q+SPLIT); both are now handled.

#define FULL  0xffffffffu
#define BTILT 4.40625f                  // 256*B = 1128.0 exact
#define THR   768
#define NCTA  8
#define SCALE 2.168404344971009e-19f    // 2^-62 exact
#define LGSUM 171.9005008f              // 248 * ln(2)
#define TXBYTES (NCTA * 67 * 4)         // 2144

// Single-thread-per-output conv (stride-1 loop; at most one tail element).
template<int SHI_S, int SHI_D, int NP>
__device__ __forceinline__ void conv_lvl(const float* __restrict__ src,
                                         float* __restrict__ dst, int tid)
{
    constexpr int SST   = SHI_S + 1;
    constexpr int DSTR  = SHI_D + 1;
    constexpr int NTASK = NP * DSTR;    // <= THR
    if (tid < NTASK) {
        const int p = tid / DSTR;
        const int j = tid - p * DSTR;
        const float* a = src + (2 * p) * SST;
        const float* b = a + SST;
        const int ilo = (j - SHI_S > 0) ? j - SHI_S : 0;
        const int ihi = (j < SHI_S) ? j : SHI_S;
        const float* ap = a + ilo;
        const float* bp = b + (j - ilo);
        const int len = ihi - ilo + 1;
        float s0 = 0.f, s1 = 0.f;
        int q = 0;
        #pragma unroll 2
        for (; q + 2 <= len; q += 2) {
            s0 = fmaf(ap[q],     bp[-q],     s0);
            s1 = fmaf(ap[q + 1], bp[-q - 1], s1);
        }
        if (q < len) s0 = fmaf(ap[q], bp[-q], s0);   // stride 1: <=1 tail
        dst[p * DSTR + j] = s0 + s1;
    }
}

// Lane-split conv: SPLIT lanes per output (power of 2), shfl-reduce.
// Sources window [SLO_S,SHI_S], dest [SLO_D,SHI_D]; optional 2^-62 scale.
template<int SLO_S, int SHI_S, int SLO_D, int SHI_D, int NP, int SPLIT, bool SC>
__device__ __forceinline__ void conv_split(const float* __restrict__ src,
                                           float* __restrict__ dst, int tid)
{
    constexpr int SST   = SHI_S - SLO_S + 1;
    constexpr int DSTR  = SHI_D - SLO_D + 1;
    constexpr int NT    = NP * DSTR * SPLIT;   // <= THR
    const bool act = tid < NT;
    const int  u   = tid / SPLIT;              // SPLIT pow2 -> shift
    const int  r   = tid - u * SPLIT;
    const int  p   = act ? u / DSTR : 0;
    const int  jj  = act ? u - p * DSTR : 0;
    const int  j   = jj + SLO_D;
    const float* a = src + (2 * p) * SST;
    const float* b = a + SST;
    const int ilo = (j - SHI_S > SLO_S) ? j - SHI_S : SLO_S;
    const int ihi = (j - SLO_S < SHI_S) ? j - SLO_S : SHI_S;
    const float* ap = a + (ilo - SLO_S) + r;
    const float* bp = b + (j - ilo - SLO_S) - r;
    const int len = act ? (ihi - ilo + 1 - r) : 0;
    float s0 = 0.f, s1 = 0.f;
    int q = 0;
    #pragma unroll 2
    for (; q + 2 * SPLIT <= len; q += 2 * SPLIT) {
        s0 = fmaf(ap[q],         bp[-q],         s0);
        s1 = fmaf(ap[q + SPLIT], bp[-q - SPLIT], s1);
    }
    // stride-SPLIT loop: up to TWO tail elements (q and q+SPLIT)
    if (q < len)         s0 = fmaf(ap[q],         bp[-q],         s0);
    if (q + SPLIT < len) s1 = fmaf(ap[q + SPLIT], bp[-q - SPLIT], s1);
    float s = s0 + s1;
    #pragma unroll
    for (int o = 1; o < SPLIT; o <<= 1) s += __shfl_xor_sync(FULL, s, o);
    if (act && r == 0) dst[p * DSTR + jj] = SC ? s * SCALE : s;
}

__global__ __launch_bounds__(THR) __cluster_dims__(NCTA, 1, 1)
void cp_kernel(const float* __restrict__ w,
               const int* __restrict__ Kp,
               float* __restrict__ out)
{
    __shared__ float A_[576];       // leaf 64x9 | V1 16x16 | V3 4x29
    __shared__ float B_[416];       // V0 32x13  | V2 8x21  | V4 2x43
    __shared__ float recv[NCTA*67]; // CTA 0: the 8 subtree polys [0,66]
    __shared__ float T1s[4 * 93];   // CTA 0: 4 polys [18,110] (scaled)
    __shared__ float T2s[2 * 125];  // CTA 0: 2 polys [66,190]
    __shared__ int   sK;
    __shared__ __align__(8) unsigned long long bar;

    cg::cluster_group cl = cg::this_cluster();
    const int rank = (int)blockIdx.x;
    const int tid  = threadIdx.x;
    const int lane = tid & 31;
    const int warp = tid >> 5;

    const unsigned int bar_u32 = (unsigned int)__cvta_generic_to_shared(&bar);

    // Rank 0: mbarrier init + expect_tx BEFORE cluster arrive.
    if (rank == 0 && tid == 0) {
        asm volatile("mbarrier.init.shared.b64 [%0], %1;"
                     :: "r"(bar_u32), "r"(1u) : "memory");
        asm volatile("mbarrier.arrive.expect_tx.shared.b64 _, [%0], %1;"
                     :: "r"(bar_u32), "r"((unsigned int)TXBYTES) : "memory");
        sK = Kp ? *Kp : 256;           // prefetch K
    }
    asm volatile("barrier.cluster.arrive.aligned;" ::: "memory");

    // ---- Leaf DP: 64 threads x 16 items, ESP_0..8 in registers ----
    if (tid < 64) {
        const float4* wp = (const float4*)(w + rank * 1024 + tid * 16);
        float c1=0,c2=0,c3=0,c4=0,c5=0,c6=0,c7=0,c8=0;
        #pragma unroll
        for (int q = 0; q < 4; ++q) {
            const float4 wv = wp[q];
            const float xs[4] = {wv.x, wv.y, wv.z, wv.w};
            #pragma unroll
            for (int k = 0; k < 4; ++k) {
                const float x = __expf(xs[k] - BTILT);
                c8 = fmaf(x, c7, c8);
                c7 = fmaf(x, c6, c7);
                c6 = fmaf(x, c5, c6);
                c5 = fmaf(x, c4, c5);
                c4 = fmaf(x, c3, c4);
                c3 = fmaf(x, c2, c3);
                c2 = fmaf(x, c1, c2);
                c1 += x;
            }
        }
        float* d = A_ + tid * 9;
        d[0]=1.f; d[1]=c1; d[2]=c2; d[3]=c3; d[4]=c4;
        d[5]=c5;  d[6]=c6; d[7]=c7; d[8]=c8;
    }
    __syncthreads();

    // ---- In-CTA ladder: 16 -> 512 items, lane-split where len is long ----
    conv_lvl  < 8, 12, 32>(A_, B_, tid);                   __syncthreads();
    conv_split<0, 12, 0, 15, 16, 2, false>(B_, A_, tid);   __syncthreads();
    conv_split<0, 15, 0, 20,  8, 4, false>(A_, B_, tid);   __syncthreads();
    conv_split<0, 20, 0, 28,  4, 4, false>(B_, A_, tid);   __syncthreads();
    conv_split<0, 28, 0, 42,  2, 8, false>(A_, B_, tid);   __syncthreads();

    // producers must not st.async before rank 0's init+expect_tx
    asm volatile("barrier.cluster.wait.aligned;" ::: "memory");

    // ---- V5: 2x[0,42] -> [0,66], 8-way split; st.async into CTA 0 ----
    {
        constexpr int SPLIT = 8;
        const bool act = tid < 67 * SPLIT;     // 536
        const int  u   = tid / SPLIT;
        const int  r   = tid - u * SPLIT;
        const int  j   = act ? u : 0;
        const float* a = B_;                   // poly 0 [0,42]
        const float* b = B_ + 43;              // poly 1
        const int ilo = (j - 42 > 0) ? j - 42 : 0;
        const int ihi = (j < 42) ? j : 42;
        const float* ap = a + ilo + r;
        const float* bp = b + (j - ilo) - r;
        const int len = act ? (ihi - ilo + 1 - r) : 0;
        float s = 0.f;
        #pragma unroll 2
        for (int q = 0; q < len; q += SPLIT) s = fmaf(ap[q], bp[-q], s);
        #pragma unroll
        for (int o = 1; o < SPLIT; o <<= 1) s += __shfl_xor_sync(FULL, s, o);
        if (act && r == 0) {
            const unsigned int laddr = (unsigned int)__cvta_generic_to_shared(
                                           &recv[rank * 67 + u]);
            asm volatile(
                "{\n\t.reg .b32 ra, rb;\n\t"
                "mapa.shared::cluster.u32 ra, %0, 0;\n\t"
                "mapa.shared::cluster.u32 rb, %1, 0;\n\t"
                "st.async.shared::cluster.mbarrier::complete_tx::bytes.b32 "
                "[ra], %2, [rb];\n\t}"
                :: "r"(laddr), "r"(bar_u32), "f"(s) : "memory");
        }
    }

    if (rank != 0) return;                     // producers: store-and-exit

    // ---- CTA 0: wait for all 2144 tx bytes (includes its own) ----
    if (tid == 0) {
        unsigned int done = 0;
        while (!done)
            asm volatile("{\n\t.reg .pred p;\n\t"
                "mbarrier.try_wait.parity.acquire.cluster.shared::cta.b64 "
                "p, [%1], %2, 0x989680;\n\t"
                "selp.b32 %0, 1, 0, p;\n\t}"
                : "=r"(done) : "r"(bar_u32), "r"(0u) : "memory");
    }
    __syncthreads();

    // ---- T1: 4 pair-convs, [0,66]^2 -> [18,110], 2-way split, x2^-62 ----
    conv_split<0, 66, 18, 110, 4, 2, true>(recv, T1s, tid);
    __syncthreads();

    // ---- T2: 2 pair-convs, [18,110]^2 -> [66,190], 2-way split ----
    conv_split<18, 110, 66, 190, 2, 2, false>(T1s, T2s, tid);
    __syncthreads();

    // ---- Final: c_K from the two [66,190] windows ----
    if (warp == 0) {
        int K = min(max(sK, 0), 256);
        const float* a = T2s;            // poly 0
        const float* b = T2s + 125;      // poly 1
        const int ilo = max(66, K - 190);
        const int ihi = min(190, K - 66);
        float s = 0.f;
        for (int i = ilo + lane; i <= ihi; i += 32)
            s += a[i - 66] * b[K - i - 66];
        #pragma unroll
        for (int o = 16; o; o >>= 1) s += __shfl_xor_sync(FULL, s, o);
        if (lane == 0)
            out[0] = __logf(s) + LGSUM + (float)K * BTILT;
    }
}

extern "C" void kernel_launch(void* const* d_in, const int* in_sizes, int n_in,
                              void* d_out, int out_size) {
    const float* w   = (const float*)d_in[0];
    const int*   Kp  = (n_in >= 2) ? (const int*)d_in[1] : nullptr;
    float*       out = (float*)d_out;
    (void)in_sizes; (void)out_size;
    cp_kernel<<<NCTA, THR>>>(w, Kp, out);
}